// round 1
// baseline (speedup 1.0000x reference)
#include <cuda_runtime.h>
#include <math_constants.h>

// Top-8 (sorted descending) along last axis of (1024, 256, 128) fp32.
// 262144 rows of 128 floats. One warp per row; each lane holds a float4.
// 8 rounds of warp-butterfly max + ballot-elect-owner invalidation.

__global__ __launch_bounds__(256) void topk8_kernel(
    const float* __restrict__ x,
    float* __restrict__ out,
    int nrows)
{
    const int warp_id = (blockIdx.x * blockDim.x + threadIdx.x) >> 5;
    const int lane = threadIdx.x & 31;
    if (warp_id >= nrows) return;

    // Coalesced: warp reads 32 x 16B = 512B = one full row.
    const float4 f = reinterpret_cast<const float4*>(x + (size_t)warp_id * 128)[lane];
    float v0 = f.x, v1 = f.y, v2 = f.z, v3 = f.w;

    float res = 0.0f;  // lanes 0..7 collect the k-th max

    #pragma unroll
    for (int k = 0; k < 8; ++k) {
        // Local max of the 4 resident values.
        float local = fmaxf(fmaxf(v0, v1), fmaxf(v2, v3));

        // Warp butterfly max: all lanes end with the row max.
        float m = local;
        #pragma unroll
        for (int o = 16; o > 0; o >>= 1)
            m = fmaxf(m, __shfl_xor_sync(0xffffffffu, m, o));

        if (lane == k) res = m;

        // Elect exactly ONE owning lane (lowest lane holding the max) and
        // invalidate exactly one copy — duplicates survive to later ranks,
        // matching top_k semantics.
        const unsigned ball = __ballot_sync(0xffffffffu, local == m);
        if (lane == (__ffs(ball) - 1)) {
            if      (v0 == m) v0 = -CUDART_INF_F;
            else if (v1 == m) v1 = -CUDART_INF_F;
            else if (v2 == m) v2 = -CUDART_INF_F;
            else              v3 = -CUDART_INF_F;
        }
    }

    // Coalesced 32B store per row from lanes 0..7.
    if (lane < 8)
        out[(size_t)warp_id * 8 + lane] = res;
}

extern "C" void kernel_launch(void* const* d_in, const int* in_sizes, int n_in,
                              void* d_out, int out_size)
{
    const float* x = (const float*)d_in[0];
    float* out = (float*)d_out;

    const int nrows = in_sizes[0] / 128;        // 1024*256 = 262144
    const int threads = 256;                    // 8 warps/block
    const int blocks = (nrows * 32 + threads - 1) / threads;

    topk8_kernel<<<blocks, threads>>>(x, out, nrows);
}

// round 2
// speedup vs baseline: 2.3357x; 2.3357x over previous
#include <cuda_runtime.h>
#include <math.h>

// Top-8 (sorted desc) along last axis of (1024,256,128) fp32 = 262144 rows.
// Thread-per-row with branchless bitonic top-8 accumulation; coalescing via
// shared-memory chunk staging (32 floats/row/pass, padded stride 36).

#define THREADS        128
#define ROWS_PER_BLOCK 128
#define NCHUNK         4      // 128 cols / 32 per chunk
#define SROW           36     // padded row stride (floats); 36 % 32 == 4 -> conflict-free

__device__ __forceinline__ void ce(float& a, float& b) {
    float hi = fmaxf(a, b);
    b = fminf(a, b);
    a = hi;
}

__global__ __launch_bounds__(THREADS) void topk8_kernel(
    const float* __restrict__ x,
    float* __restrict__ out,
    int nrows)
{
    __shared__ float s[ROWS_PER_BLOCK * SROW];   // 18432 B static

    const int tid  = threadIdx.x;
    const int row0 = blockIdx.x * ROWS_PER_BLOCK;

    float r0 = -INFINITY, r1 = -INFINITY, r2 = -INFINITY, r3 = -INFINITY;
    float r4 = -INFINITY, r5 = -INFINITY, r6 = -INFINITY, r7 = -INFINITY;

    const float4* gx = reinterpret_cast<const float4*>(x);

    #pragma unroll
    for (int c = 0; c < NCHUNK; ++c) {
        // ---- stage chunk c: 128 rows x 32 floats, fully coalesced LDG.128 ----
        #pragma unroll
        for (int i = 0; i < 8; ++i) {
            const int idx = tid + i * THREADS;     // 0..1023 float4 slots
            const int r   = idx >> 3;              // row within block
            const int c4  = idx & 7;               // float4 within chunk
            float4 v = gx[(size_t)(row0 + r) * 32 + c * 8 + c4];
            *reinterpret_cast<float4*>(&s[r * SROW + c4 * 4]) = v;
        }
        __syncthreads();

        // ---- merge: thread tid owns row (row0 + tid) ----
        const float4* sr = reinterpret_cast<const float4*>(&s[tid * SROW]);
        #pragma unroll
        for (int j = 0; j < 8; ++j) {
            float4 q = sr[j];
            // sort4 descending: q.x >= q.y >= q.z >= q.w   (5 CE)
            ce(q.x, q.y); ce(q.z, q.w);
            ce(q.x, q.z); ce(q.y, q.w);
            ce(q.y, q.z);
            // Batcher combine: top-8 of (r desc-8) U (q desc-4 padded with -inf)
            r4 = fmaxf(r4, q.w);
            r5 = fmaxf(r5, q.z);
            r6 = fmaxf(r6, q.y);
            r7 = fmaxf(r7, q.x);
            // bitonic cleanup (3 stages, 12 CE) -> r sorted descending again
            ce(r0, r4); ce(r1, r5); ce(r2, r6); ce(r3, r7);
            ce(r0, r2); ce(r1, r3); ce(r4, r6); ce(r5, r7);
            ce(r0, r1); ce(r2, r3); ce(r4, r5); ce(r6, r7);
        }
        __syncthreads();   // buffer reused next chunk
    }

    // ---- coalesced output: 2 x STG.128 per row ----
    const int myrow = row0 + tid;
    if (myrow < nrows) {
        float4* po = reinterpret_cast<float4*>(out + (size_t)myrow * 8);
        po[0] = make_float4(r0, r1, r2, r3);
        po[1] = make_float4(r4, r5, r6, r7);
    }
}

extern "C" void kernel_launch(void* const* d_in, const int* in_sizes, int n_in,
                              void* d_out, int out_size)
{
    const float* x = (const float*)d_in[0];
    float* out = (float*)d_out;

    const int nrows  = in_sizes[0] / 128;                 // 262144
    const int blocks = (nrows + ROWS_PER_BLOCK - 1) / ROWS_PER_BLOCK;  // 2048

    topk8_kernel<<<blocks, THREADS>>>(x, out, nrows);
}

// round 4
// speedup vs baseline: 2.4504x; 1.0491x over previous
#include <cuda_runtime.h>
#include <cstdint>
#include <math.h>

// Top-8 (sorted desc) along last axis of (1024,256,128) fp32 = 262144 rows.
// Thread-per-row bitonic top-8; warp-scoped cp.async double-buffered staging.
// Each warp owns 32 rows and a private smem slice -> __syncwarp only, no
// block barriers; chunk c+1 streams via LDGSTS while chunk c is merged.

#define THREADS        128
#define WARPS          4
#define ROWS_PER_WARP  32
#define ROWS_PER_BLOCK 128
#define NCHUNK         4      // 128 cols / 32 floats per chunk
#define SROW           36     // padded row stride; 36 % 32 == 4 -> conflict-free LDS/STS.128

__device__ __forceinline__ void ce(float& a, float& b) {
    float hi = fmaxf(a, b);
    b = fminf(a, b);
    a = hi;
}

__device__ __forceinline__ void cp_async16(unsigned int dst, const void* src) {
    asm volatile("cp.async.cg.shared.global [%0], [%1], 16;\n" :: "r"(dst), "l"(src));
}
__device__ __forceinline__ void cp_commit() {
    asm volatile("cp.async.commit_group;\n" ::);
}
template <int N>
__device__ __forceinline__ void cp_wait() {
    asm volatile("cp.async.wait_group %0;\n" :: "n"(N));
}

__global__ __launch_bounds__(THREADS) void topk8_kernel(
    const float* __restrict__ x,
    float* __restrict__ out,
    int nrows)
{
    // [buf][warp][row*SROW + col]  -> 2*4*32*36*4 = 36864 B
    __shared__ float s[2][WARPS][ROWS_PER_WARP * SROW];

    const int tid = threadIdx.x;
    const int w   = tid >> 5;
    const int l   = tid & 31;
    const int row0 = blockIdx.x * ROWS_PER_BLOCK + w * ROWS_PER_WARP;

    const float4* __restrict__ gx = reinterpret_cast<const float4*>(x);

    // Producer slots: idx = l + 32*i ; r = idx>>3 ; c4 = idx&7.
    // 8-lane phase => same r, c4 0..7 covers a full 128B line; SROW=36 keeps
    // STS.128 (via cp.async) and LDS.128 conflict-free per phase.

    auto load_chunk = [&](int c, int b) {
        #pragma unroll
        for (int i = 0; i < 8; ++i) {
            const int idx = l + 32 * i;
            const int r   = idx >> 3;
            const int c4  = idx & 7;
            int grow = row0 + r;
            if (grow > nrows - 1) grow = nrows - 1;   // defensive clamp
            unsigned int dst = (unsigned int)__cvta_generic_to_shared(
                &s[b][w][r * SROW + c4 * 4]);
            cp_async16(dst, gx + (size_t)grow * 32 + c * 8 + c4);
        }
        cp_commit();
    };

    float r0 = -INFINITY, r1 = -INFINITY, r2 = -INFINITY, r3 = -INFINITY;
    float r4 = -INFINITY, r5 = -INFINITY, r6 = -INFINITY, r7 = -INFINITY;

    // Prime pipeline: chunks 0 and 1 in flight.
    load_chunk(0, 0);
    load_chunk(1, 1);

    #pragma unroll
    for (int c = 0; c < NCHUNK; ++c) {
        if (c < NCHUNK - 1) cp_wait<1>(); else cp_wait<0>();
        __syncwarp();

        // ---- consumer: thread l merges its row from buffer c&1 ----
        const float* sr = &s[c & 1][w][l * SROW];
        #pragma unroll
        for (int j = 0; j < 8; ++j) {
            float4 q = *reinterpret_cast<const float4*>(sr + j * 4);
            // sort4 descending (5 CE)
            ce(q.x, q.y); ce(q.z, q.w);
            ce(q.x, q.z); ce(q.y, q.w);
            ce(q.y, q.z);
            // combine: keep top-8 of (r desc-8) U (q desc-4)
            r4 = fmaxf(r4, q.w);
            r5 = fmaxf(r5, q.z);
            r6 = fmaxf(r6, q.y);
            r7 = fmaxf(r7, q.x);
            // bitonic cleanup (12 CE) -> r sorted descending again
            ce(r0, r4); ce(r1, r5); ce(r2, r6); ce(r3, r7);
            ce(r0, r2); ce(r1, r3); ce(r4, r6); ce(r5, r7);
            ce(r0, r1); ce(r2, r3); ce(r4, r5); ce(r6, r7);
        }

        __syncwarp();                    // all lanes done reading buf (c&1)
        if (c + 2 < NCHUNK)
            load_chunk(c + 2, c & 1);    // refill the buffer just drained
    }

    const int myrow = row0 + l;
    if (myrow < nrows) {
        float4* po = reinterpret_cast<float4*>(out + (size_t)myrow * 8);
        po[0] = make_float4(r0, r1, r2, r3);
        po[1] = make_float4(r4, r5, r6, r7);
    }
}

extern "C" void kernel_launch(void* const* d_in, const int* in_sizes, int n_in,
                              void* d_out, int out_size)
{
    const float* x = (const float*)d_in[0];
    float* out = (float*)d_out;

    const int nrows  = in_sizes[0] / 128;                              // 262144
    const int blocks = (nrows + ROWS_PER_BLOCK - 1) / ROWS_PER_BLOCK;  // 2048

    topk8_kernel<<<blocks, THREADS>>>(x, out, nrows);
}

// round 5
// speedup vs baseline: 2.5203x; 1.0285x over previous
#include <cuda_runtime.h>
#include <cstdint>
#include <math.h>

// Top-8 (sorted desc) along last axis of (1024,256,128) fp32 = 262144 rows.
// Thread-per-row bitonic top-8; warp-scoped cp.async double-buffered staging.
// R5: 16-float chunks (8 stages) + launch_bounds(128,10) -> 40 warps/SM.

#define THREADS        128
#define WARPS          4
#define ROWS_PER_WARP  32
#define ROWS_PER_BLOCK 128
#define NCHUNK         8      // 128 cols / 16 floats per chunk
#define CHUNKW4        4      // float4s per row per chunk
#define SROW           20     // padded stride; 20 % 32 lane pattern conflict-free LDS.128

__device__ __forceinline__ void ce(float& a, float& b) {
    float hi = fmaxf(a, b);
    b = fminf(a, b);
    a = hi;
}

__device__ __forceinline__ void cp_async16(unsigned int dst, const void* src) {
    asm volatile("cp.async.cg.shared.global [%0], [%1], 16;\n" :: "r"(dst), "l"(src));
}
__device__ __forceinline__ void cp_commit() {
    asm volatile("cp.async.commit_group;\n" ::);
}
template <int N>
__device__ __forceinline__ void cp_wait() {
    asm volatile("cp.async.wait_group %0;\n" :: "n"(N));
}

__global__ __launch_bounds__(THREADS, 10) void topk8_kernel(
    const float* __restrict__ x,
    float* __restrict__ out,
    int nrows)
{
    // [buf][warp][row*SROW + col] -> 2*4*32*20*4 = 20480 B
    __shared__ float s[2][WARPS][ROWS_PER_WARP * SROW];

    const int tid = threadIdx.x;
    const int w   = tid >> 5;
    const int l   = tid & 31;
    const int row0 = blockIdx.x * ROWS_PER_BLOCK + w * ROWS_PER_WARP;

    const float4* __restrict__ gx = reinterpret_cast<const float4*>(x);

    // Producer: 32 rows x 4 float4 = 128 slots / 32 lanes = 4 cp.async per lane.
    auto load_chunk = [&](int c, int b) {
        #pragma unroll
        for (int i = 0; i < 4; ++i) {
            const int idx = l + 32 * i;
            const int r   = idx >> 2;          // row within warp tile
            const int c4  = idx & 3;           // float4 within chunk
            unsigned int dst = (unsigned int)__cvta_generic_to_shared(
                &s[b][w][r * SROW + c4 * 4]);
            cp_async16(dst, gx + (size_t)(row0 + r) * 32 + c * CHUNKW4 + c4);
        }
        cp_commit();
    };

    float r0 = -INFINITY, r1 = -INFINITY, r2 = -INFINITY, r3 = -INFINITY;
    float r4 = -INFINITY, r5 = -INFINITY, r6 = -INFINITY, r7 = -INFINITY;

    load_chunk(0, 0);
    load_chunk(1, 1);

    #pragma unroll
    for (int c = 0; c < NCHUNK; ++c) {
        if (c < NCHUNK - 1) cp_wait<1>(); else cp_wait<0>();
        __syncwarp();

        const float* sr = &s[c & 1][w][l * SROW];
        #pragma unroll
        for (int j = 0; j < CHUNKW4; ++j) {
            float4 q = *reinterpret_cast<const float4*>(sr + j * 4);
            // sort4 descending (5 CE)
            ce(q.x, q.y); ce(q.z, q.w);
            ce(q.x, q.z); ce(q.y, q.w);
            ce(q.y, q.z);
            // combine: L_i = max(r_i, q_rev_i) keeps top-8 multiset, bitonic
            r4 = fmaxf(r4, q.w);
            r5 = fmaxf(r5, q.z);
            r6 = fmaxf(r6, q.y);
            r7 = fmaxf(r7, q.x);
            // bitonic merge-8 cleanup (12 CE) -> sorted descending
            ce(r0, r4); ce(r1, r5); ce(r2, r6); ce(r3, r7);
            ce(r0, r2); ce(r1, r3); ce(r4, r6); ce(r5, r7);
            ce(r0, r1); ce(r2, r3); ce(r4, r5); ce(r6, r7);
        }

        __syncwarp();                    // all lanes done reading buf (c&1)
        if (c + 2 < NCHUNK)
            load_chunk(c + 2, c & 1);    // refill drained buffer
    }

    const int myrow = row0 + l;
    if (myrow < nrows) {
        float4* po = reinterpret_cast<float4*>(out + (size_t)myrow * 8);
        po[0] = make_float4(r0, r1, r2, r3);
        po[1] = make_float4(r4, r5, r6, r7);
    }
}

extern "C" void kernel_launch(void* const* d_in, const int* in_sizes, int n_in,
                              void* d_out, int out_size)
{
    const float* x = (const float*)d_in[0];
    float* out = (float*)d_out;

    const int nrows  = in_sizes[0] / 128;                              // 262144
    const int blocks = (nrows + ROWS_PER_BLOCK - 1) / ROWS_PER_BLOCK;  // 2048

    topk8_kernel<<<blocks, THREADS>>>(x, out, nrows);
}